// round 3
// baseline (speedup 1.0000x reference)
#include <cuda_runtime.h>

#define B_ 128
#define T_ 1024
#define N_ 64

// Per-batch losses; reduced deterministically by a second kernel.
__device__ float g_loss[B_];

typedef unsigned long long u64;

__device__ __forceinline__ u64 pack2(float lo, float hi) {
    u64 d;
    asm("mov.b64 %0, {%1, %2};" : "=l"(d)
        : "r"(__float_as_uint(lo)), "r"(__float_as_uint(hi)));
    return d;
}
__device__ __forceinline__ float unpack_sum(u64 v) {
    unsigned a, b;
    asm("mov.b64 {%0, %1}, %2;" : "=r"(a), "=r"(b) : "l"(v));
    return __uint_as_float(a) + __uint_as_float(b);
}
__device__ __forceinline__ u64 ffma2(u64 a, u64 b, u64 c) {
    u64 d;
    asm("fma.rn.f32x2 %0, %1, %2, %3;" : "=l"(d) : "l"(a), "l"(b), "l"(c));
    return d;
}
__device__ __forceinline__ u64 fadd2(u64 a, u64 b) {
    u64 d;
    asm("add.rn.f32x2 %0, %1, %2;" : "=l"(d) : "l"(a), "l"(b));
    return d;
}

// 128 threads: thread = (output state j = tid>>1, K-half h = tid&1).
// Each thread does half of the length-64 dot product (8x LDS.128 + 16x FFMA2),
// halves combined with one shfl.bfly(1) (partner is the adjacent lane).
// Renormalization (rcp + log MUFUs + a0 broadcast) only every 4th step.
__global__ void __launch_bounds__(2 * N_, 1) crf_forward_kernel(
    const float* __restrict__ pot,     // (B,T,N)
    const int*   __restrict__ tags,    // (B,T)
    const int*   __restrict__ seqlen,  // (B,)
    const float* __restrict__ ck,      // (N,N)
    const float* __restrict__ sw)      // (B,)
{
    const int tid = threadIdx.x;
    const int b   = blockIdx.x;
    const int j   = tid >> 1;          // output state
    const int h   = tid & 1;           // which half of the K dimension
    const int len = seqlen[b];

    __shared__ __align__(16) float abuf[2][N_];
    __shared__ float red[N_];

    // This thread's 16 packed E-pairs: for m=0..7, k=2m+h covers rows 4k..4k+3.
    // (Interleaved halves: h=0 and h=1 read 16B-offset addresses -> disjoint banks.)
    u64 Ec[16];
#pragma unroll
    for (int m = 0; m < 8; ++m) {
        int k = 2 * m + h;
        Ec[2 * m]     = pack2(__expf(ck[(4 * k)     * N_ + j]),
                              __expf(ck[(4 * k + 1) * N_ + j]));
        Ec[2 * m + 1] = pack2(__expf(ck[(4 * k + 2) * N_ + j]),
                              __expf(ck[(4 * k + 3) * N_ + j]));
    }

    const float* Pb   = pot  + (size_t)b * T_ * N_;
    const int*   tagb = tags + b * T_;

    // ---------------- sequence score ----------------
    float ss = 0.f;
    for (int t = tid; t < len; t += 2 * N_) {
        int tg = tagb[t];
        ss += Pb[t * N_ + tg];
        if (t >= 1) ss += ck[tagb[t - 1] * N_ + tg];
    }
    red[tid % N_] = 0.f;
    __syncthreads();
    if (tid < N_) red[tid] = ss;
    __syncthreads();
    if (tid >= N_) red[tid - N_] += ss;   // safe: one writer per slot
    __syncthreads();
#pragma unroll
    for (int off = N_ / 2; off >= 1; off >>= 1) {
        if (tid < off) red[tid] += red[tid + off];
        __syncthreads();
    }
    const float seq_score = red[0];

    // ---------------- forward scan (linear domain + running log offset) ----
    float c = Pb[0];
    if (h == 0) abuf[0][j] = __expf(Pb[j] - c);
    __syncthreads();

    // Prefetch potentials two steps ahead, branch-free via clamping.
    float p_cur = Pb[1 * N_ + j];                       // len >= T/2 >= 2
    float p_nxt = Pb[min(2, len - 1) * N_ + j];

    int cur = 0;
    for (int t = 1; t < len; ++t) {
        float p_pref = Pb[min(t + 2, len - 1) * N_ + j];

        const float* rd = abuf[cur];
        float epot  = __expf(p_cur);
        float scale = epot;
        if ((t & 3) == 0) {                 // renormalize every 4th step
            float a0 = rd[0];               // broadcast LDS
            scale = __fdividef(1.0f, a0) * epot;
            c += __logf(a0);                // independent accumulator chain
        }

        // Half dot product: 8x LDS.128 (k = 2m+h), 16x FFMA2, 4 accumulators.
        const ulonglong2* a4 = (const ulonglong2*)rd;
        u64 acc0 = 0ull, acc1 = 0ull, acc2 = 0ull, acc3 = 0ull;
#pragma unroll
        for (int m = 0; m < 8; ++m) {
            ulonglong2 v = a4[2 * m + h];   // floats 4k..4k+3
            if (m & 1) {
                acc2 = ffma2(v.x, Ec[2 * m],     acc2);
                acc3 = ffma2(v.y, Ec[2 * m + 1], acc3);
            } else {
                acc0 = ffma2(v.x, Ec[2 * m],     acc0);
                acc1 = ffma2(v.y, Ec[2 * m + 1], acc1);
            }
        }
        acc0 = fadd2(acc0, acc1);
        acc2 = fadd2(acc2, acc3);
        acc0 = fadd2(acc0, acc2);
        float sh = unpack_sum(acc0);

        // Combine the two K-halves: partner is the adjacent lane (same warp).
        sh += __shfl_xor_sync(0xffffffffu, sh, 1);

        if (h == 0) abuf[cur ^ 1][j] = sh * scale;
        __syncthreads();
        cur ^= 1;
        p_cur = p_nxt;
        p_nxt = p_pref;
    }

    // log_norm = c + log(sum_j a[j])
    if (tid < N_) red[tid] = abuf[cur][tid];
    __syncthreads();
#pragma unroll
    for (int off = N_ / 2; off >= 1; off >>= 1) {
        if (tid < off) red[tid] += red[tid + off];
        __syncthreads();
    }

    if (tid == 0) {
        float log_norm = c + logf(red[0]);
        g_loss[b] = -(seq_score - log_norm) * sw[b];
    }
}

__global__ void crf_finalize_kernel(float* __restrict__ out)
{
    __shared__ float r[B_];
    int j = threadIdx.x;
    r[j] = g_loss[j];
    __syncthreads();
#pragma unroll
    for (int off = B_ / 2; off >= 1; off >>= 1) {
        if (j < off) r[j] += r[j + off];
        __syncthreads();
    }
    if (j == 0) out[0] = r[0] * (1.0f / (float)B_);
}

extern "C" void kernel_launch(void* const* d_in, const int* in_sizes, int n_in,
                              void* d_out, int out_size)
{
    const float* pot    = (const float*)d_in[0];
    const int*   tags   = (const int*)  d_in[1];
    const int*   seqlen = (const int*)  d_in[2];
    const float* ck     = (const float*)d_in[3];
    const float* sw     = (const float*)d_in[4];

    crf_forward_kernel<<<B_, 2 * N_>>>(pot, tags, seqlen, ck, sw);
    crf_finalize_kernel<<<1, B_>>>((float*)d_out);
}